// round 5
// baseline (speedup 1.0000x reference)
#include <cuda_runtime.h>
#include <cstdint>

#define BB 4
#define CH 1024
#define HH 50
#define WW 50
#define KK 512
#define NPIX (HH*WW)              // 2500
#define GPTS 8                    // grid points per axis

// NHWC-transposed features: [B][H][W][C]  (41 MB device-global scratch)
__device__ __align__(16) float FT[BB * HH * WW * CH];

// ---------------------------------------------------------------------------
// Kernel 1: NCHW -> NHWC transpose, float4 both sides. (measured ~14us)
// ---------------------------------------------------------------------------
__global__ __launch_bounds__(256)
void transpose_kernel(const float* __restrict__ f) {
    __shared__ __align__(16) float tile[32][133];
    const int b  = blockIdx.z;
    const int p0 = blockIdx.x * 128;
    const int c0 = blockIdx.y * 32;
    const int t  = threadIdx.x;

    const float* fb = f + (size_t)b * CH * NPIX + (size_t)c0 * NPIX;
    #pragma unroll
    for (int j = 0; j < 4; j++) {
        int idx = t + j * 256;
        int c = idx >> 5;
        int q = idx & 31;
        int p = p0 + 4 * q;
        float4 v = make_float4(0.f, 0.f, 0.f, 0.f);
        if (p < NPIX) v = *(const float4*)(fb + (size_t)c * NPIX + p);
        tile[c][4 * q + 0] = v.x;
        tile[c][4 * q + 1] = v.y;
        tile[c][4 * q + 2] = v.z;
        tile[c][4 * q + 3] = v.w;
    }
    __syncthreads();
    float* ob = FT + (size_t)b * NPIX * CH + c0;
    #pragma unroll
    for (int j = 0; j < 4; j++) {
        int idx = t + j * 256;
        int p = idx >> 3;
        int g = idx & 7;
        if (p0 + p < NPIX) {
            float4 v;
            v.x = tile[4 * g + 0][p];
            v.y = tile[4 * g + 1][p];
            v.z = tile[4 * g + 2][p];
            v.w = tile[4 * g + 3][p];
            *(float4*)(ob + (size_t)(p0 + p) * CH + 4 * g) = v;
        }
    }
}

// ---------------------------------------------------------------------------
// Kernel 2: fused RoIAlign + 2x2 avg pool, pooled-row-split.
// Grid (K, 2, 4): ch-half (512 ch) x row-split z.
//   z=0: pooled rows 0-1 (grid rows 0-2)
//   z=1: pooled rows 2-3 (grid rows 2-4)
//   z=2: pooled rows 4-5 (grid rows 4-6)
//   z=3: pooled row  6   (grid rows 6-7)
// 256 threads, 2 ch/thread; acc <= 14 float2 = 28 regs -> 4 CTAs/SM.
// ---------------------------------------------------------------------------
template<int G0, int PR>
__device__ __forceinline__
void roi_half(const float* __restrict__ rois, float* __restrict__ out,
              int k, int chHalf, int tid,
              float* sbuf,
              float* s_wx, float* s_wy, float* s_vx, float* s_vy,
              int* s_x0, int* s_y0, int* s_b) {
    constexpr int PRW = PR * 7;

    if (tid < GPTS) {
        float x1 = __ldg(&rois[k * 5 + 1]) * 0.0625f;
        float y1 = __ldg(&rois[k * 5 + 2]) * 0.0625f;
        float x2 = __ldg(&rois[k * 5 + 3]) * 0.0625f;
        float y2 = __ldg(&rois[k * 5 + 4]) * 0.0625f;
        float bh = fmaxf(y2 - y1, 0.0f) * (1.0f / 7.0f);
        float bw = fmaxf(x2 - x1, 0.0f) * (1.0f / 7.0f);
        float xv = x1 + (float)tid * bw;
        float yv = y1 + (float)tid * bh;
        s_vx[tid] = (xv >= 0.0f && xv < (float)WW) ? 1.0f : 0.0f;
        s_vy[tid] = (yv >= 0.0f && yv < (float)HH) ? 1.0f : 0.0f;
        int x0 = (int)floorf(xv);  x0 = min(max(x0, 0), WW - 2);
        int y0 = (int)floorf(yv);  y0 = min(max(y0, 0), HH - 2);
        s_x0[tid] = x0;  s_y0[tid] = y0;
        s_wx[tid] = xv - (float)x0;
        s_wy[tid] = yv - (float)y0;
        if (tid == 0) *s_b = (int)__ldg(&rois[k * 5 + 0]);
    }
    __syncthreads();

    const int c0 = chHalf * 512 + tid * 2;
    const float* bptr = FT + (size_t)(*s_b) * (NPIX * CH) + c0;

    float2 acc[PRW];
    #pragma unroll
    for (int i = 0; i < PRW; i++) { acc[i].x = 0.0f; acc[i].y = 0.0f; }

    #pragma unroll
    for (int g = 0; g <= PR; g++) {           // local grid row
        const int   gy = G0 + g;
        const int   y0 = s_y0[gy];
        const float wy = s_wy[gy];
        const float vy = s_vy[gy];
        const float* rp = bptr + (size_t)y0 * (WW * CH);
        #pragma unroll
        for (int gx = 0; gx < GPTS; gx++) {
            const int   x0 = s_x0[gx];
            const float wx = s_wx[gx];
            const float sc = 0.25f * vy * s_vx[gx];

            const float* p = rp + x0 * CH;
            float2 v00 = *(const float2*)(p);
            float2 v01 = *(const float2*)(p + CH);
            float2 v10 = *(const float2*)(p + WW * CH);
            float2 v11 = *(const float2*)(p + WW * CH + CH);

            float w00 = (1.0f - wy) * (1.0f - wx) * sc;
            float w01 = (1.0f - wy) * wx * sc;
            float w10 = wy * (1.0f - wx) * sc;
            float w11 = wy * wx * sc;

            float ax = v00.x*w00 + v01.x*w01 + v10.x*w10 + v11.x*w11;
            float ay = v00.y*w00 + v01.y*w01 + v10.y*w10 + v11.y*w11;

            // scatter to local pooled rows (g-1, g) x cols (gx-1, gx)
            if (g >= 1) {
                if (gx >= 1) { acc[(g-1)*7 + (gx-1)].x += ax; acc[(g-1)*7 + (gx-1)].y += ay; }
                if (gx <  7) { acc[(g-1)*7 +  gx   ].x += ax; acc[(g-1)*7 +  gx   ].y += ay; }
            }
            if (g < PR) {
                if (gx >= 1) { acc[ g   *7 + (gx-1)].x += ax; acc[ g   *7 + (gx-1)].y += ay; }
                if (gx <  7) { acc[ g   *7 +  gx   ].x += ax; acc[ g   *7 +  gx   ].y += ay; }
            }
        }
    }

    // ---- staged output writes: this CTA owns out[k, chHalf*512 + 0..511,
    // pooled rows G0..G0+PR-1, :]. Stage 128 channels at a time.
    float* outb = out + (size_t)k * (CH * 49) + (size_t)chHalf * (512 * 49) + G0 * 7;
    #pragma unroll
    for (int sub = 0; sub < 4; sub++) {
        if ((tid >> 6) == sub) {
            int cl = tid * 2 - sub * 128;   // 0..126 even
            #pragma unroll
            for (int i = 0; i < PRW; i++) {
                sbuf[(cl    ) * PRW + i] = acc[i].x;
                sbuf[(cl + 1) * PRW + i] = acc[i].y;
            }
        }
        __syncthreads();
        float* outc = outb + (size_t)sub * (128 * 49);
        constexpr int N = 128 * PRW;
        #pragma unroll
        for (int j = 0; j < (N + 255) / 256; j++) {
            int i = tid + j * 256;
            if (i < N) {
                int c   = i / PRW;           // compile-time magic division
                int rem = i - c * PRW;
                outc[c * 49 + rem] = sbuf[i];
            }
        }
        __syncthreads();
    }
}

__global__ __launch_bounds__(256, 4)
void roi_pool_kernel(const float* __restrict__ rois, float* __restrict__ out) {
    const int k      = blockIdx.x;
    const int chHalf = blockIdx.y;
    const int z      = blockIdx.z;
    const int tid    = threadIdx.x;

    __shared__ float sbuf[128 * 14];          // 7 KB staging (max PRW=14)
    __shared__ float s_wx[GPTS], s_wy[GPTS], s_vx[GPTS], s_vy[GPTS];
    __shared__ int   s_x0[GPTS], s_y0[GPTS];
    __shared__ int   s_b;

    if (z == 0)      roi_half<0, 2>(rois, out, k, chHalf, tid, sbuf, s_wx, s_wy, s_vx, s_vy, s_x0, s_y0, &s_b);
    else if (z == 1) roi_half<2, 2>(rois, out, k, chHalf, tid, sbuf, s_wx, s_wy, s_vx, s_vy, s_x0, s_y0, &s_b);
    else if (z == 2) roi_half<4, 2>(rois, out, k, chHalf, tid, sbuf, s_wx, s_wy, s_vx, s_vy, s_x0, s_y0, &s_b);
    else             roi_half<6, 1>(rois, out, k, chHalf, tid, sbuf, s_wx, s_wy, s_vx, s_vy, s_x0, s_y0, &s_b);
}

// ---------------------------------------------------------------------------
extern "C" void kernel_launch(void* const* d_in, const int* in_sizes, int n_in,
                              void* d_out, int out_size) {
    const float* features = (const float*)d_in[0];
    const float* rois     = (const float*)d_in[1];
    float* out            = (float*)d_out;

    dim3 tgrid((NPIX + 127) / 128, CH / 32, BB);   // (20, 32, 4)
    transpose_kernel<<<tgrid, 256>>>(features);
    roi_pool_kernel<<<dim3(KK, 2, 4), 256>>>(rois, out);
}

// round 6
// speedup vs baseline: 2.1785x; 2.1785x over previous
#include <cuda_runtime.h>
#include <cuda_fp16.h>
#include <cstdint>

#define BB 4
#define CH 1024
#define HH 50
#define WW 50
#define KK 512
#define NPIX (HH*WW)              // 2500
#define GPTS 8                    // grid points per axis

// NHWC-transposed features in fp16: [B][H][W][C]  (20.5 MB scratch)
__device__ __align__(16) __half FT[BB * HH * WW * CH];

// ---------------------------------------------------------------------------
// Kernel 1: NCHW fp32 -> NHWC fp16 transpose-convert.
// Tile: 32 channels x 128 pixels, float4 loads, uint4 (8xhalf) stores.
// ---------------------------------------------------------------------------
__global__ __launch_bounds__(256)
void transpose_kernel(const float* __restrict__ f) {
    __shared__ __align__(16) float tile[32][133];
    const int b  = blockIdx.z;
    const int p0 = blockIdx.x * 128;
    const int c0 = blockIdx.y * 32;
    const int t  = threadIdx.x;

    const float* fb = f + (size_t)b * CH * NPIX + (size_t)c0 * NPIX;
    #pragma unroll
    for (int j = 0; j < 4; j++) {
        int idx = t + j * 256;
        int c = idx >> 5;
        int q = idx & 31;
        int p = p0 + 4 * q;
        float4 v = make_float4(0.f, 0.f, 0.f, 0.f);
        if (p < NPIX) v = *(const float4*)(fb + (size_t)c * NPIX + p);
        tile[c][4 * q + 0] = v.x;
        tile[c][4 * q + 1] = v.y;
        tile[c][4 * q + 2] = v.z;
        tile[c][4 * q + 3] = v.w;
    }
    __syncthreads();

    __half* ob = FT + (size_t)b * NPIX * CH + c0;
    // 512 units: 128 pixels x 4 groups of 8 channels, 16B stores
    #pragma unroll
    for (int j = 0; j < 2; j++) {
        int idx = t + j * 256;
        int p = idx >> 2;            // 0..127
        int g = idx & 3;             // 0..3
        if (p0 + p < NPIX) {
            __half2 h0 = __floats2half2_rn(tile[8*g + 0][p], tile[8*g + 1][p]);
            __half2 h1 = __floats2half2_rn(tile[8*g + 2][p], tile[8*g + 3][p]);
            __half2 h2 = __floats2half2_rn(tile[8*g + 4][p], tile[8*g + 5][p]);
            __half2 h3 = __floats2half2_rn(tile[8*g + 6][p], tile[8*g + 7][p]);
            uint4 v;
            v.x = *(const unsigned int*)&h0;
            v.y = *(const unsigned int*)&h1;
            v.z = *(const unsigned int*)&h2;
            v.w = *(const unsigned int*)&h3;
            *(uint4*)(ob + (size_t)(p0 + p) * CH + 8 * g) = v;
        }
    }
}

// ---------------------------------------------------------------------------
// Kernel 2: fused RoIAlign (8x8 grid) + 2x2 avg pool -> (K,C,7,7)
// Grid (K, 2): each block covers 512 channels of one roi. 256 threads,
// 2 channels/thread (half2 taps -> fp32 math), 49 float2 accumulators,
// smem weight table (LDS.128/point), chunked coalesced float4 stores.
// ---------------------------------------------------------------------------
__global__ __launch_bounds__(256, 2)
void roi_pool_kernel(const float* __restrict__ rois, float* __restrict__ out) {
    const int k     = blockIdx.x;
    const int chunk = blockIdx.y;          // 0 or 1: channel half
    const int tid   = threadIdx.x;

    __shared__ __align__(16) float sbuf[128 * 49];     // 25 KB staging
    __shared__ __align__(16) float s_w[GPTS][GPTS][4]; // folded weights, 4 KB
    __shared__ float s_wx[GPTS], s_wy[GPTS], s_vx[GPTS], s_vy[GPTS];
    __shared__ int   s_x0[GPTS], s_y0[GPTS];
    __shared__ int   s_b;

    if (tid < GPTS) {
        float x1 = __ldg(&rois[k * 5 + 1]) * 0.0625f;
        float y1 = __ldg(&rois[k * 5 + 2]) * 0.0625f;
        float x2 = __ldg(&rois[k * 5 + 3]) * 0.0625f;
        float y2 = __ldg(&rois[k * 5 + 4]) * 0.0625f;
        float bh = fmaxf(y2 - y1, 0.0f) * (1.0f / 7.0f);
        float bw = fmaxf(x2 - x1, 0.0f) * (1.0f / 7.0f);
        float xv = x1 + (float)tid * bw;
        float yv = y1 + (float)tid * bh;
        s_vx[tid] = (xv >= 0.0f && xv < (float)WW) ? 1.0f : 0.0f;
        s_vy[tid] = (yv >= 0.0f && yv < (float)HH) ? 1.0f : 0.0f;
        int x0 = (int)floorf(xv);  x0 = min(max(x0, 0), WW - 2);
        int y0 = (int)floorf(yv);  y0 = min(max(y0, 0), HH - 2);
        s_x0[tid] = x0;  s_y0[tid] = y0;
        s_wx[tid] = xv - (float)x0;
        s_wy[tid] = yv - (float)y0;
        if (tid == 0) s_b = (int)__ldg(&rois[k * 5 + 0]);
    }
    __syncthreads();

    // precompute folded bilinear weights (uniform across channels)
    if (tid < 64) {
        int gy = tid >> 3, gx = tid & 7;
        float wy = s_wy[gy], wx = s_wx[gx];
        float sc = 0.25f * s_vy[gy] * s_vx[gx];
        s_w[gy][gx][0] = (1.0f - wy) * (1.0f - wx) * sc;
        s_w[gy][gx][1] = (1.0f - wy) * wx * sc;
        s_w[gy][gx][2] = wy * (1.0f - wx) * sc;
        s_w[gy][gx][3] = wy * wx * sc;
    }
    __syncthreads();

    const int c0 = chunk * 512 + tid * 2;
    const __half* bptr = FT + (size_t)s_b * (NPIX * CH) + c0;

    float2 acc[49];
    #pragma unroll
    for (int i = 0; i < 49; i++) { acc[i].x = 0.0f; acc[i].y = 0.0f; }

    #pragma unroll
    for (int gy = 0; gy < GPTS; gy++) {
        const int y0 = s_y0[gy];
        const __half* rp = bptr + (size_t)y0 * (WW * CH);
        #pragma unroll
        for (int gx = 0; gx < GPTS; gx++) {
            const int x0 = s_x0[gx];
            const float4 w = *(const float4*)&s_w[gy][gx][0];

            const __half* p = rp + x0 * CH;
            float2 f00 = __half22float2(*(const __half2*)(p));
            float2 f01 = __half22float2(*(const __half2*)(p + CH));
            float2 f10 = __half22float2(*(const __half2*)(p + WW * CH));
            float2 f11 = __half22float2(*(const __half2*)(p + WW * CH + CH));

            float ax = f00.x*w.x + f01.x*w.y + f10.x*w.z + f11.x*w.w;
            float ay = f00.y*w.x + f01.y*w.y + f10.y*w.z + f11.y*w.w;

            if (gy >= 1 && gx >= 1) { acc[(gy-1)*7 + (gx-1)].x += ax; acc[(gy-1)*7 + (gx-1)].y += ay; }
            if (gy >= 1 && gx <  7) { acc[(gy-1)*7 +  gx   ].x += ax; acc[(gy-1)*7 +  gx   ].y += ay; }
            if (gy <  7 && gx >= 1) { acc[ gy   *7 + (gx-1)].x += ax; acc[ gy   *7 + (gx-1)].y += ay; }
            if (gy <  7 && gx <  7) { acc[ gy   *7 +  gx   ].x += ax; acc[ gy   *7 +  gx   ].y += ay; }
        }
    }

    // ---- staged, coalesced output writes (unchanged from R4) -----------
    float* outk = out + (size_t)k * (CH * 49) + (size_t)chunk * (512 * 49);
    #pragma unroll
    for (int sub = 0; sub < 4; sub++) {
        if ((tid >> 6) == sub) {
            int cl = tid * 2 - sub * 128;   // 0..126, even
            #pragma unroll
            for (int i = 0; i < 49; i++) {
                sbuf[(cl    ) * 49 + i] = acc[i].x;
                sbuf[(cl + 1) * 49 + i] = acc[i].y;
            }
        }
        __syncthreads();
        const float4* s4 = (const float4*)sbuf;
        float4* o4 = (float4*)(outk + sub * 6272);
        #pragma unroll
        for (int j = 0; j < 7; j++) {
            int i = tid + j * 256;
            if (i < 1568) o4[i] = s4[i];
        }
        __syncthreads();
    }
}

// ---------------------------------------------------------------------------
extern "C" void kernel_launch(void* const* d_in, const int* in_sizes, int n_in,
                              void* d_out, int out_size) {
    const float* features = (const float*)d_in[0];
    const float* rois     = (const float*)d_in[1];
    float* out            = (float*)d_out;

    dim3 tgrid((NPIX + 127) / 128, CH / 32, BB);   // (20, 32, 4)
    transpose_kernel<<<tgrid, 256>>>(features);
    roi_pool_kernel<<<dim3(KK, 2), 256>>>(rois, out);
}